// round 1
// baseline (speedup 1.0000x reference)
#include <cuda_runtime.h>
#include <cuda_bf16.h>
#include <cstdint>

#define NDIM 8192
#define SDIM 2
#define BDIM 8
#define CIN  32
#define COUT 32
#define JDIM 256   // BDIM * COUT

// Scratch for Y[s][m][b*32+o] (16.8 MB) — static device array (no allocs allowed)
__device__ float g_Y[(size_t)SDIM * NDIM * JDIM];

// ---------------------------------------------------------------------------
// Kernel A: Y[s,m,b*32+o] = sum_c x[b,m,c] * W[s,o,c]
// grid (NDIM/8, BDIM, SDIM), block 256
// ---------------------------------------------------------------------------
__global__ void prep_Y_kernel(const float* __restrict__ x,
                              const float* __restrict__ W) {
    __shared__ float Wsh[32][33];   // padded: conflict-free on [o][c] with o across lanes
    __shared__ float xsh[8][32];

    const int s  = blockIdx.z;
    const int b  = blockIdx.y;
    const int m0 = blockIdx.x * 8;
    const int t  = threadIdx.x;
    const int mi = t >> 5;
    const int o  = t & 31;

    // W[s] is 32x32 = 1024 floats
    for (int idx = t; idx < 1024; idx += 256)
        Wsh[idx >> 5][idx & 31] = W[s * 1024 + idx];
    xsh[mi][o] = x[((size_t)b * NDIM + (m0 + mi)) * CIN + o];
    __syncthreads();

    float sum = 0.0f;
#pragma unroll
    for (int c = 0; c < 32; c++)
        sum += xsh[mi][c] * Wsh[o][c];

    g_Y[((size_t)s * NDIM + (m0 + mi)) * JDIM + b * COUT + o] = sum;
}

// ---------------------------------------------------------------------------
// Kernel B: out[n, J] = sum_s supports[s] @ Y[s]   (J = b*32+o, 256 cols)
// BM=64, BN=128, BK=32, 128 threads, 8x8 thread tile, f32x2 packed FMA
// grid (2 colTiles, 128 rowTiles)
// ---------------------------------------------------------------------------

__device__ __forceinline__ unsigned long long ffma2(unsigned long long a,
                                                    unsigned long long b,
                                                    unsigned long long c) {
    unsigned long long d;
    asm("fma.rn.f32x2 %0, %1, %2, %3;" : "=l"(d) : "l"(a), "l"(b), "l"(c));
    return d;
}

__device__ __forceinline__ unsigned long long pack2(float v) {
    unsigned long long d;
    asm("mov.b64 %0, {%1, %2};" : "=l"(d) : "f"(v), "f"(v));
    return d;
}

__device__ __forceinline__ void unpack2(unsigned long long v, float& lo, float& hi) {
    asm("mov.b64 {%0, %1}, %2;" : "=f"(lo), "=f"(hi) : "l"(v));
}

#define BM 64
#define BN 128
#define BK 32
#define KTILES ((SDIM * NDIM) / BK)   // 512

__global__ __launch_bounds__(128, 3)
void graphconv_main_kernel(const float* __restrict__ supports,
                           const float* __restrict__ bias,
                           float* __restrict__ out) {
    __shared__ float As[BK][BM + 4];   // transposed A tile, pad 4 (keeps 16B align)
    __shared__ float Bs[BK][BN];

    const int t  = threadIdx.x;
    const int tx = t & 15;             // 16 col-groups of 8
    const int ty = t >> 4;             // 8 row-groups of 8
    const int colTile = blockIdx.x;    // 0..1
    const int n0 = blockIdx.y * BM;
    const int J0 = colTile * BN;

    // A load mapping: 512 float4 / 128 thr -> 4 each. f = t + 128*i
    //   rowA = f>>3 (8 float4 per 32-float row), c4a = f&7
    // B load mapping: 1024 float4 / 128 thr -> 8 each. f = t + 128*i
    //   rowB = f>>5, c4b = f&31
    float4 regA[4];
    float4 regB[8];

    unsigned long long acc[8][4];
#pragma unroll
    for (int i = 0; i < 8; i++)
#pragma unroll
        for (int p = 0; p < 4; p++) acc[i][p] = 0ULL;

    // ---- prefetch tile 0 ----
    {
        const int kt = 0;
        const int s  = kt >> 8;
        const int k0 = (kt & 255) * BK;
        const float* Abase = supports + (size_t)s * NDIM * NDIM;
        const float* Bbase = g_Y + ((size_t)s * NDIM + k0) * JDIM + J0;
#pragma unroll
        for (int i = 0; i < 4; i++) {
            int f = t + 128 * i;
            regA[i] = *(const float4*)(Abase + (size_t)(n0 + (f >> 3)) * NDIM + k0 + (f & 7) * 4);
        }
#pragma unroll
        for (int i = 0; i < 8; i++) {
            int f = t + 128 * i;
            regB[i] = *(const float4*)(Bbase + (size_t)(f >> 5) * JDIM + (f & 31) * 4);
        }
    }

    for (int kt = 0; kt < KTILES; kt++) {
        __syncthreads();   // previous compute done before overwriting smem

        // store current tile to smem (A transposed)
#pragma unroll
        for (int i = 0; i < 4; i++) {
            int f = t + 128 * i;
            int rowA = f >> 3, c4a = f & 7;
            As[c4a * 4 + 0][rowA] = regA[i].x;
            As[c4a * 4 + 1][rowA] = regA[i].y;
            As[c4a * 4 + 2][rowA] = regA[i].z;
            As[c4a * 4 + 3][rowA] = regA[i].w;
        }
#pragma unroll
        for (int i = 0; i < 8; i++) {
            int f = t + 128 * i;
            *(float4*)&Bs[f >> 5][(f & 31) * 4] = regB[i];
        }
        __syncthreads();

        // prefetch next tile into registers (overlaps with compute below)
        if (kt + 1 < KTILES) {
            const int ktn = kt + 1;
            const int s   = ktn >> 8;
            const int k0  = (ktn & 255) * BK;
            const float* Abase = supports + (size_t)s * NDIM * NDIM;
            const float* Bbase = g_Y + ((size_t)s * NDIM + k0) * JDIM + J0;
#pragma unroll
            for (int i = 0; i < 4; i++) {
                int f = t + 128 * i;
                regA[i] = *(const float4*)(Abase + (size_t)(n0 + (f >> 3)) * NDIM + k0 + (f & 7) * 4);
            }
#pragma unroll
            for (int i = 0; i < 8; i++) {
                int f = t + 128 * i;
                regB[i] = *(const float4*)(Bbase + (size_t)(f >> 5) * JDIM + (f & 31) * 4);
            }
        }

        // compute
#pragma unroll 8
        for (int k = 0; k < BK; k++) {
            float4 a0 = *(const float4*)&As[k][ty * 8];
            float4 a1 = *(const float4*)&As[k][ty * 8 + 4];
            ulonglong2 bp0 = *(const ulonglong2*)&Bs[k][tx * 8];
            ulonglong2 bp1 = *(const ulonglong2*)&Bs[k][tx * 8 + 4];

            unsigned long long A2[8];
            A2[0] = pack2(a0.x); A2[1] = pack2(a0.y);
            A2[2] = pack2(a0.z); A2[3] = pack2(a0.w);
            A2[4] = pack2(a1.x); A2[5] = pack2(a1.y);
            A2[6] = pack2(a1.z); A2[7] = pack2(a1.w);

#pragma unroll
            for (int i = 0; i < 8; i++) {
                acc[i][0] = ffma2(A2[i], bp0.x, acc[i][0]);
                acc[i][1] = ffma2(A2[i], bp0.y, acc[i][1]);
                acc[i][2] = ffma2(A2[i], bp1.x, acc[i][2]);
                acc[i][3] = ffma2(A2[i], bp1.y, acc[i][3]);
            }
        }
    }

    // ---- epilogue: unpack, add bias, store ----
    const int J  = J0 + tx * 8;       // 8-aligned -> all 8 cols within one b
    const int bI = J >> 5;
    const int o0 = J & 31;

    float bv[8];
#pragma unroll
    for (int jj = 0; jj < 8; jj++) bv[jj] = bias[o0 + jj];

#pragma unroll
    for (int i = 0; i < 8; i++) {
        const int n = n0 + ty * 8 + i;
        float v[8];
#pragma unroll
        for (int p = 0; p < 4; p++) unpack2(acc[i][p], v[2 * p], v[2 * p + 1]);
        float4 r0 = make_float4(v[0] + bv[0], v[1] + bv[1], v[2] + bv[2], v[3] + bv[3]);
        float4 r1 = make_float4(v[4] + bv[4], v[5] + bv[5], v[6] + bv[6], v[7] + bv[7]);
        float* op = out + ((size_t)bI * NDIM + n) * COUT + o0;
        *(float4*)op       = r0;
        *(float4*)(op + 4) = r1;
    }
}

// ---------------------------------------------------------------------------
extern "C" void kernel_launch(void* const* d_in, const int* in_sizes, int n_in,
                              void* d_out, int out_size) {
    const float* x        = (const float*)d_in[0];  // (8, 8192, 32)
    const float* supports = (const float*)d_in[1];  // (2, 8192, 8192)
    const float* W        = (const float*)d_in[2];  // (2, 32, 32)
    const float* bias     = (const float*)d_in[3];  // (32,)
    float* out = (float*)d_out;                     // (8, 8192, 32)

    (void)in_sizes; (void)n_in; (void)out_size;

    prep_Y_kernel<<<dim3(NDIM / 8, BDIM, SDIM), 256>>>(x, W);

    dim3 grid(JDIM / BN, NDIM / BM);   // (2, 128)
    graphconv_main_kernel<<<grid, 128>>>(supports, bias, out);
}

// round 5
// speedup vs baseline: 4.0556x; 4.0556x over previous
#include <cuda_runtime.h>
#include <cuda_bf16.h>
#include <cstdint>

#define NN    8192
#define SDIM  2
#define JDIM  256
#define COUT  32

#define BM 128
#define BN 128
#define BK 32
#define KT 512          // SDIM*NN / BK
#define SK 40           // padded smem row stride in bf16 elems (80B, 16B-aligned, conflict-free)

// Pre-split B operand: Yt[s][j][k] = Y[s][k][j], bf16 hi/lo (8.4 MB each)
__device__ __align__(256) __nv_bfloat16 g_Yt_hi[(size_t)SDIM * JDIM * NN];
__device__ __align__(256) __nv_bfloat16 g_Yt_lo[(size_t)SDIM * JDIM * NN];

// ---------------------------------------------------------------------------
// helpers
// ---------------------------------------------------------------------------
__device__ __forceinline__ uint32_t smem_u32(const void* p) {
    uint32_t a;
    asm("{ .reg .u64 t; cvta.to.shared.u64 t, %1; cvt.u32.u64 %0, t; }"
        : "=r"(a) : "l"(p));
    return a;
}

// pack two floats to bf16x2 (element0 = a, element1 = b)
__device__ __forceinline__ uint32_t bf2(float a, float b) {
    uint32_t r;
    asm("cvt.rn.bf16x2.f32 %0, %1, %2;" : "=r"(r) : "f"(b), "f"(a));
    return r;
}

__device__ __forceinline__ void ldsm4(uint32_t* r, uint32_t addr) {
    asm volatile("ldmatrix.sync.aligned.m8n8.x4.shared.b16 {%0,%1,%2,%3}, [%4];"
                 : "=r"(r[0]), "=r"(r[1]), "=r"(r[2]), "=r"(r[3]) : "r"(addr));
}

__device__ __forceinline__ void mma_bf16(float* c, const uint32_t* a, const uint32_t* b) {
    asm volatile(
        "mma.sync.aligned.m16n8k16.row.col.f32.bf16.bf16.f32 "
        "{%0,%1,%2,%3},{%4,%5,%6,%7},{%8,%9},{%0,%1,%2,%3};"
        : "+f"(c[0]), "+f"(c[1]), "+f"(c[2]), "+f"(c[3])
        : "r"(a[0]), "r"(a[1]), "r"(a[2]), "r"(a[3]), "r"(b[0]), "r"(b[1]));
}

// ---------------------------------------------------------------------------
// Kernel A: Yt_hi/lo[s][j][k] = split_bf16( sum_c x[b,k,c] * W[s,o,c] ),
//           j = b*32+o.  grid (64 kblocks, 8 b, 2 s), 256 threads.
// ---------------------------------------------------------------------------
__global__ void prep_Yt_kernel(const float* __restrict__ x,
                               const float* __restrict__ W) {
    __shared__ float Wsh[COUT][33];
    __shared__ __align__(16) float xsh[128][32];
    __shared__ __align__(16) __nv_bfloat16 yhi[COUT][128];
    __shared__ __align__(16) __nv_bfloat16 ylo[COUT][128];

    const int s  = blockIdx.z;
    const int b  = blockIdx.y;
    const int kb = blockIdx.x;
    const int t  = threadIdx.x;

    for (int i = t; i < 1024; i += 256) Wsh[i >> 5][i & 31] = W[s * 1024 + i];

    const float4* xbase = (const float4*)(x + ((size_t)b * NN + (size_t)kb * 128) * 32);
#pragma unroll
    for (int i = 0; i < 4; i++) {
        int f = t + 256 * i;
        ((float4*)&xsh[0][0])[f] = xbase[f];
    }
    __syncthreads();

    const int o = t & 31;
#pragma unroll
    for (int i = 0; i < 16; i++) {
        int ki = (t >> 5) + i * 8;
        float sum = 0.0f;
#pragma unroll
        for (int c = 0; c < 32; c++) sum += xsh[ki][c] * Wsh[o][c];
        __nv_bfloat16 h = __float2bfloat16(sum);
        float hf = __bfloat162float(h);
        __nv_bfloat16 l = __float2bfloat16(sum - hf);
        yhi[o][ki] = h;
        ylo[o][ki] = l;
    }
    __syncthreads();

    // writeback: each thread owns 16 elements = TWO uint4 (uint4 = 8 bf16).
    // (Round-4 bug: only the first uint4 was written -> half of g_Yt stayed zero.)
    const int oo  = t >> 3;
    const int seg = t & 7;
    size_t base = ((size_t)(s * JDIM + b * 32 + oo)) * NN + (size_t)kb * 128 + seg * 16;
    *(uint4*)(&g_Yt_hi[base])     = *(const uint4*)(&yhi[oo][seg * 16]);
    *(uint4*)(&g_Yt_hi[base + 8]) = *(const uint4*)(&yhi[oo][seg * 16 + 8]);
    *(uint4*)(&g_Yt_lo[base])     = *(const uint4*)(&ylo[oo][seg * 16]);
    *(uint4*)(&g_Yt_lo[base + 8]) = *(const uint4*)(&ylo[oo][seg * 16 + 8]);
}

// ---------------------------------------------------------------------------
// Main GEMM via mma.sync bf16 (3-pass hi/lo split):
// out[n, j] = sum_s sum_k supports[s,n,k] * Y[s,k,j] + bias[j&31]
// Grid: 128 CTAs = (64 m-tiles) x (2 j-halves). 256 threads = 8 warps (2x4).
// Each warp: 64x32 tile = 4 m-tiles(16) x 4 n-tiles(8).
// ---------------------------------------------------------------------------
__global__ __launch_bounds__(256, 1)
void graphconv_hmma_kernel(const float* __restrict__ supports,
                           const float* __restrict__ bias,
                           float* __restrict__ out) {
    __shared__ __align__(16) __nv_bfloat16 Ahi[BM][SK];
    __shared__ __align__(16) __nv_bfloat16 Alo[BM][SK];
    __shared__ __align__(16) __nv_bfloat16 Bhi[BN][SK];
    __shared__ __align__(16) __nv_bfloat16 Blo[BN][SK];

    const int t     = threadIdx.x;
    const int wid   = t >> 5;
    const int lane  = t & 31;
    const int mtile = blockIdx.x >> 1;
    const int jhalf = blockIdx.x & 1;
    const int n0    = mtile * BM;
    const int wrow  = wid >> 2;         // 0..1 -> 64 m rows each
    const int wcol  = wid & 3;          // 0..3 -> 32 n cols each

    // gmem load mapping: each thread owns half a row (16 k elems)
    const int row  = t >> 1;            // 0..127
    const int koff = (t & 1) * 16;      // 0 or 16

    float4 ra[4];                       // 16 fp32 A elems
    uint4  rbh[2], rbl[2];              // 16 bf16 hi + 16 bf16 lo B elems

    float acc[4][4][4];
#pragma unroll
    for (int i = 0; i < 4; i++)
#pragma unroll
        for (int j = 0; j < 4; j++)
#pragma unroll
            for (int p = 0; p < 4; p++) acc[i][j][p] = 0.0f;

    // ldmatrix source addresses (per thread, fixed parts)
    const int arow = wrow * 64 + (lane & 15);
    const int acol = (lane >> 4) * 8;
    const uint32_t aHiAddr = smem_u32(&Ahi[arow][acol]);
    const uint32_t aLoAddr = smem_u32(&Alo[arow][acol]);
    const int brow = wcol * 32 + (lane & 7) + ((lane >> 4) << 3);
    const int bcol = ((lane >> 3) & 1) << 3;
    const uint32_t bHiAddr = smem_u32(&Bhi[brow][bcol]);
    const uint32_t bLoAddr = smem_u32(&Blo[brow][bcol]);

#define LOAD_A(kt)                                                              \
    {                                                                           \
        const int sidx = (kt) >> 8;                                             \
        const int k0   = ((kt) & 255) * BK;                                     \
        const float* ap = supports + (size_t)sidx * NN * NN                     \
                        + (size_t)(n0 + row) * NN + k0 + koff;                  \
        ra[0] = *(const float4*)(ap + 0);                                       \
        ra[1] = *(const float4*)(ap + 4);                                       \
        ra[2] = *(const float4*)(ap + 8);                                       \
        ra[3] = *(const float4*)(ap + 12);                                      \
    }

#define LOAD_B(kt)                                                              \
    {                                                                           \
        const int sidx = (kt) >> 8;                                             \
        const int k0   = ((kt) & 255) * BK;                                     \
        const size_t boff = ((size_t)(sidx * JDIM + jhalf * 128 + row)) * NN    \
                          + k0 + koff;                                          \
        rbh[0] = *(const uint4*)(g_Yt_hi + boff);                               \
        rbh[1] = *(const uint4*)(g_Yt_hi + boff + 8);                           \
        rbl[0] = *(const uint4*)(g_Yt_lo + boff);                               \
        rbl[1] = *(const uint4*)(g_Yt_lo + boff + 8);                           \
    }

    LOAD_A(0);
    LOAD_B(0);

    for (int kt = 0; kt < KT; kt++) {
        __syncthreads();   // previous compute done before overwriting smem

        // ---- STS: convert A to bf16 hi/lo, store B directly ----
        {
            uint32_t h[8], g[8];
#pragma unroll
            for (int q = 0; q < 4; q++) {
                float4 f = ra[q];
                uint32_t h01 = bf2(f.x, f.y);
                uint32_t h23 = bf2(f.z, f.w);
                float l0 = f.x - __uint_as_float(h01 << 16);
                float l1 = f.y - __uint_as_float(h01 & 0xffff0000u);
                float l2 = f.z - __uint_as_float(h23 << 16);
                float l3 = f.w - __uint_as_float(h23 & 0xffff0000u);
                h[2 * q] = h01; h[2 * q + 1] = h23;
                g[2 * q] = bf2(l0, l1); g[2 * q + 1] = bf2(l2, l3);
            }
            *(uint4*)&Ahi[row][koff]     = make_uint4(h[0], h[1], h[2], h[3]);
            *(uint4*)&Ahi[row][koff + 8] = make_uint4(h[4], h[5], h[6], h[7]);
            *(uint4*)&Alo[row][koff]     = make_uint4(g[0], g[1], g[2], g[3]);
            *(uint4*)&Alo[row][koff + 8] = make_uint4(g[4], g[5], g[6], g[7]);
            *(uint4*)&Bhi[row][koff]     = rbh[0];
            *(uint4*)&Bhi[row][koff + 8] = rbh[1];
            *(uint4*)&Blo[row][koff]     = rbl[0];
            *(uint4*)&Blo[row][koff + 8] = rbl[1];
        }
        __syncthreads();

        // ---- prefetch next tile into regs (overlaps with compute) ----
        if (kt + 1 < KT) {
            LOAD_A(kt + 1);
            LOAD_B(kt + 1);
        }

        // ---- compute: 2 k-steps of 16 ----
#pragma unroll
        for (int ks = 0; ks < 2; ks++) {
            uint32_t afh[4][4], afl[4][4];
#pragma unroll
            for (int mt = 0; mt < 4; mt++) {
                ldsm4(afh[mt], aHiAddr + mt * (16 * SK * 2) + ks * 32);
                ldsm4(afl[mt], aLoAddr + mt * (16 * SK * 2) + ks * 32);
            }
            uint32_t bfh[2][4], bfl[2][4];
#pragma unroll
            for (int p = 0; p < 2; p++) {
                ldsm4(bfh[p], bHiAddr + p * (16 * SK * 2) + ks * 32);
                ldsm4(bfl[p], bLoAddr + p * (16 * SK * 2) + ks * 32);
            }
#pragma unroll
            for (int mt = 0; mt < 4; mt++) {
#pragma unroll
                for (int nt = 0; nt < 4; nt++) {
                    const uint32_t* bh = &bfh[nt >> 1][(nt & 1) * 2];
                    const uint32_t* bl = &bfl[nt >> 1][(nt & 1) * 2];
                    mma_bf16(acc[mt][nt], afh[mt], bh);
                    mma_bf16(acc[mt][nt], afh[mt], bl);
                    mma_bf16(acc[mt][nt], afl[mt], bh);
                }
            }
        }
    }

    // ---- epilogue: C frag -> out (+bias) ----
    // j = jhalf*128 + wcol*32 + (nt*8 + (lane&3)*2); b = j>>5, o = j&31
    {
        const int g    = lane >> 2;
        const int qq   = lane & 3;
        const int bidx = jhalf * 4 + wcol;
        float* obase = out + (size_t)bidx * NN * COUT;
#pragma unroll
        for (int mt = 0; mt < 4; mt++) {
            const int m = n0 + wrow * 64 + mt * 16 + g;
#pragma unroll
            for (int nt = 0; nt < 4; nt++) {
                const int o = nt * 8 + qq * 2;
                const float2 bv = *(const float2*)(bias + o);
                float2 v0, v1;
                v0.x = acc[mt][nt][0] + bv.x;
                v0.y = acc[mt][nt][1] + bv.y;
                v1.x = acc[mt][nt][2] + bv.x;
                v1.y = acc[mt][nt][3] + bv.y;
                *(float2*)(obase + (size_t)m * COUT + o)       = v0;
                *(float2*)(obase + (size_t)(m + 8) * COUT + o) = v1;
            }
        }
    }
}

// ---------------------------------------------------------------------------
extern "C" void kernel_launch(void* const* d_in, const int* in_sizes, int n_in,
                              void* d_out, int out_size) {
    const float* x        = (const float*)d_in[0];  // (8, 8192, 32)
    const float* supports = (const float*)d_in[1];  // (2, 8192, 8192)
    const float* W        = (const float*)d_in[2];  // (2, 32, 32)
    const float* bias     = (const float*)d_in[3];  // (32,)
    float* out = (float*)d_out;                     // (8, 8192, 32)
    (void)in_sizes; (void)n_in; (void)out_size;

    prep_Yt_kernel<<<dim3(64, 8, 2), 256>>>(x, W);
    graphconv_hmma_kernel<<<128, 256>>>(supports, bias, out);
}